// round 1
// baseline (speedup 1.0000x reference)
#include <cuda_runtime.h>
#include <math.h>

#define NN 100000
#define EE 150000
#define DD 512
#define HH 8
#define DHH 64

#define BM 64
#define BN 64
#define BK 16

// ---------------- scratch (static __device__ globals; no allocation) -------
__device__ float g_h_o[(size_t)NN * DD];    // projected openie feats
__device__ float g_h_e[(size_t)NN * DD];    // projected entity feats
__device__ float g_out0[(size_t)NN * DD];   // metapath 0 output (pre-relu sums)
__device__ float g_out1[(size_t)NN * DD];   // metapath 1 output (pre-relu sums)
__device__ float g_asrc[NN * HH];
__device__ float g_adst[NN * HH];
__device__ float g_amax[NN * HH];
__device__ float g_denom[NN * HH];
__device__ float g_ebuf[EE * HH];           // alpha, then exp values
__device__ float g_ksum[2 * DD];            // sum_n tanh(relu(out)@W+b)
__device__ float g_musum[2 * DD];           // sum_n relu(out)

// ---------------- helpers --------------------------------------------------
__device__ __forceinline__ void atomicMaxF(float* addr, float val) {
    int old = __float_as_int(*addr);
    while (__int_as_float(old) < val) {
        int assumed = old;
        old = atomicCAS((int*)addr, assumed, __float_as_int(val));
        if (old == assumed) break;
    }
}

// ---------------- generic zero ---------------------------------------------
__global__ void zero_buf(float* p, long n) {
    long i = (long)blockIdx.x * blockDim.x + threadIdx.x;
    long stride = (long)gridDim.x * blockDim.x;
    for (; i < n; i += stride) p[i] = 0.0f;
}

__global__ void init_edge_state(float* amax, float* denom, int n) {
    int i = blockIdx.x * blockDim.x + threadIdx.x;
    if (i < n) { amax[i] = -INFINITY; denom[i] = 0.0f; }
}

// ---------------- tiled SGEMM: C = A[M,512] @ W[512,512] (+bias) ----------
// MODE 0: store C with bias.
// MODE 1: A is relu'd at load; epilogue accumulates sum_rows tanh(acc+bias)
//         into ksum (C not written).
template <int MODE>
__global__ void gemm_kernel(const float* __restrict__ A,
                            const float* __restrict__ W,
                            const float* __restrict__ bias,
                            float* __restrict__ C, int M,
                            float* __restrict__ ksum_out) {
    __shared__ float As[BK][BM];
    __shared__ float Bs[BK][BN];
    __shared__ float red[16][BN];

    int tid = threadIdx.x;            // 0..255
    int tx = tid & 15, ty = tid >> 4;
    int m0 = blockIdx.y * BM;
    int n0 = blockIdx.x * BN;

    int arow = tid >> 2;              // 0..63
    int acol = (tid & 3) * 4;
    int brow = tid >> 4;              // 0..15
    int bcol = (tid & 15) * 4;

    float acc[4][4];
#pragma unroll
    for (int i = 0; i < 4; i++)
#pragma unroll
        for (int j = 0; j < 4; j++) acc[i][j] = 0.0f;

    for (int k0 = 0; k0 < DD; k0 += BK) {
        int gm = m0 + arow;
        float4 av;
        if (gm < M) {
            av = *(const float4*)(A + (size_t)gm * DD + k0 + acol);
        } else {
            av = make_float4(0.f, 0.f, 0.f, 0.f);
        }
        if (MODE == 1) {
            av.x = fmaxf(av.x, 0.f); av.y = fmaxf(av.y, 0.f);
            av.z = fmaxf(av.z, 0.f); av.w = fmaxf(av.w, 0.f);
        }
        As[acol + 0][arow] = av.x;
        As[acol + 1][arow] = av.y;
        As[acol + 2][arow] = av.z;
        As[acol + 3][arow] = av.w;

        float4 bv = *(const float4*)(W + (size_t)(k0 + brow) * DD + n0 + bcol);
        *(float4*)(&Bs[brow][bcol]) = bv;
        __syncthreads();

#pragma unroll
        for (int k = 0; k < BK; k++) {
            float4 a4 = *(const float4*)(&As[k][ty * 4]);
            float4 b4 = *(const float4*)(&Bs[k][tx * 4]);
            float ar[4] = {a4.x, a4.y, a4.z, a4.w};
            float br[4] = {b4.x, b4.y, b4.z, b4.w};
#pragma unroll
            for (int i = 0; i < 4; i++)
#pragma unroll
                for (int j = 0; j < 4; j++) acc[i][j] += ar[i] * br[j];
        }
        __syncthreads();
    }

    float4 bb = *(const float4*)(bias + n0 + tx * 4);
    float bre[4] = {bb.x, bb.y, bb.z, bb.w};

    if (MODE == 0) {
#pragma unroll
        for (int i = 0; i < 4; i++) {
            int row = m0 + ty * 4 + i;
            if (row < M) {
                float4 v = make_float4(acc[i][0] + bre[0], acc[i][1] + bre[1],
                                       acc[i][2] + bre[2], acc[i][3] + bre[3]);
                *(float4*)(C + (size_t)row * DD + n0 + tx * 4) = v;
            }
        }
    } else {
        float part[4] = {0.f, 0.f, 0.f, 0.f};
#pragma unroll
        for (int i = 0; i < 4; i++) {
            int row = m0 + ty * 4 + i;
            if (row < M) {
#pragma unroll
                for (int j = 0; j < 4; j++)
                    part[j] += tanhf(acc[i][j] + bre[j]);
            }
        }
#pragma unroll
        for (int j = 0; j < 4; j++) red[ty][tx * 4 + j] = part[j];
        __syncthreads();
        if (tid < BN) {
            float s = 0.f;
#pragma unroll
            for (int r = 0; r < 16; r++) s += red[r][tid];
            atomicAdd(&ksum_out[n0 + tid], s);
        }
    }
}

// ---------------- per-node attention dots: a[n,h] = <h[n,h,:], att[h,:]> ----
__global__ void compute_ah(const float* __restrict__ hmat,
                           const float* __restrict__ att,
                           float* __restrict__ a, int n_nodes) {
    int gt = blockIdx.x * blockDim.x + threadIdx.x;
    int warp = gt >> 5;
    int lane = threadIdx.x & 31;
    if (warp >= n_nodes) return;
    int base = lane * 16;                   // h = lane>>2
    const float4* hp = (const float4*)(hmat + (size_t)warp * DD + base);
    const float4* ap = (const float4*)(att + base);
    float s = 0.f;
#pragma unroll
    for (int q = 0; q < 4; q++) {
        float4 hv = hp[q];
        float4 av = ap[q];
        s += hv.x * av.x + hv.y * av.y + hv.z * av.z + hv.w * av.w;
    }
    s += __shfl_xor_sync(0xffffffffu, s, 1);
    s += __shfl_xor_sync(0xffffffffu, s, 2);
    if ((lane & 3) == 0) a[warp * HH + (lane >> 2)] = s;
}

// ---------------- edge pass 1: alpha + segment max --------------------------
__global__ void edge_alpha_max(const int* __restrict__ src,
                               const int* __restrict__ dst,
                               const float* __restrict__ asrc,
                               const float* __restrict__ adst,
                               float* __restrict__ alpha,
                               float* __restrict__ amax, int ne) {
    int i = blockIdx.x * blockDim.x + threadIdx.x;
    if (i >= ne * HH) return;
    int e = i >> 3, h = i & 7;
    float v = asrc[src[e] * HH + h] + adst[dst[e] * HH + h];
    v = (v > 0.f) ? v : 0.2f * v;          // leaky_relu 0.2
    alpha[i] = v;
    atomicMaxF(&amax[dst[e] * HH + h], v);
}

// ---------------- edge pass 2: exp + segment sum -----------------------------
__global__ void edge_exp_sum(const int* __restrict__ dst,
                             float* __restrict__ alpha,
                             const float* __restrict__ amax,
                             float* __restrict__ denom, int ne) {
    int i = blockIdx.x * blockDim.x + threadIdx.x;
    if (i >= ne * HH) return;
    int e = i >> 3, h = i & 7;
    float ex = expf(alpha[i] - amax[dst[e] * HH + h]);
    alpha[i] = ex;
    atomicAdd(&denom[dst[e] * HH + h], ex);
}

// ---------------- edge pass 3: weighted message scatter ----------------------
__global__ void edge_scatter(const int* __restrict__ src,
                             const int* __restrict__ dst,
                             const float* __restrict__ hsrc,
                             const float* __restrict__ exbuf,
                             const float* __restrict__ denom,
                             float* __restrict__ outb, int ne) {
    int gt = blockIdx.x * blockDim.x + threadIdx.x;
    int e = gt >> 5;
    int lane = threadIdx.x & 31;
    if (e >= ne) return;
    int s = src[e], d = dst[e];
    int h = lane >> 2;
    float w = exbuf[e * HH + h] / (denom[d * HH + h] + 1e-16f);
    const float4* hp = (const float4*)(hsrc + (size_t)s * DD + lane * 16);
    float* op = outb + (size_t)d * DD + lane * 16;
#pragma unroll
    for (int q = 0; q < 4; q++) {
        float4 v = hp[q];
        atomicAdd(op + q * 4 + 0, v.x * w);
        atomicAdd(op + q * 4 + 1, v.y * w);
        atomicAdd(op + q * 4 + 2, v.z * w);
        atomicAdd(op + q * 4 + 3, v.w * w);
    }
}

// ---------------- column means of relu(out) ----------------------------------
__global__ void mu_kernel(const float* __restrict__ outb,
                          float* __restrict__ musum, int M) {
    int f = threadIdx.x;                   // 512 threads
    int chunk = (M + gridDim.x - 1) / gridDim.x;
    int r0 = blockIdx.x * chunk;
    int r1 = min(M, r0 + chunk);
    float acc = 0.f;
    for (int r = r0; r < r1; r++)
        acc += fmaxf(outb[(size_t)r * DD + f], 0.f);
    atomicAdd(&musum[f], acc);
}

// ---------------- final semantic attention + pool + linear -------------------
__global__ void final_kernel(const float* __restrict__ qsem,
                             const float* __restrict__ linw,
                             const float* __restrict__ linb,
                             float* __restrict__ out) {
    __shared__ float sh[DD];
    __shared__ float sv[2];
    int f = threadIdx.x;                   // 512 threads
    const float invN = 1.0f / (float)NN;
    float q = qsem[f];
    float v0 = g_ksum[f] * invN * q;
    float v1 = g_ksum[DD + f] * invN * q;

    sh[f] = v0; __syncthreads();
    for (int s = 256; s > 0; s >>= 1) { if (f < s) sh[f] += sh[f + s]; __syncthreads(); }
    if (f == 0) sv[0] = sh[0];
    __syncthreads();
    sh[f] = v1; __syncthreads();
    for (int s = 256; s > 0; s >>= 1) { if (f < s) sh[f] += sh[f + s]; __syncthreads(); }
    if (f == 0) sv[1] = sh[0];
    __syncthreads();

    float s0 = sv[0], s1 = sv[1];
    float mx = fmaxf(s0, s1);
    float e0 = expf(s0 - mx), e1 = expf(s1 - mx);
    float sem0 = e0 / (e0 + e1), sem1 = e1 / (e0 + e1);

    float pooled = (sem0 * g_musum[f] + sem1 * g_musum[DD + f]) * invN;
    float w0 = pooled * linw[f * 2 + 0];
    float w1 = pooled * linw[f * 2 + 1];

    sh[f] = w0; __syncthreads();
    for (int s = 256; s > 0; s >>= 1) { if (f < s) sh[f] += sh[f + s]; __syncthreads(); }
    if (f == 0) out[0] = sh[0] + linb[0];
    __syncthreads();
    sh[f] = w1; __syncthreads();
    for (int s = 256; s > 0; s >>= 1) { if (f < s) sh[f] += sh[f + s]; __syncthreads(); }
    if (f == 0) out[1] = sh[0] + linb[1];
}

// ---------------- host launcher ---------------------------------------------
extern "C" void kernel_launch(void* const* d_in, const int* in_sizes, int n_in,
                              void* d_out, int out_size) {
    const float* x_o  = (const float*)d_in[0];
    const float* x_e  = (const float*)d_in[1];
    const int*   e2o  = (const int*)d_in[2];   // [2,E]
    const int*   o2o  = (const int*)d_in[3];
    const float* powm = (const float*)d_in[4];
    const float* pob  = (const float*)d_in[5];
    const float* pewm = (const float*)d_in[6];
    const float* peb  = (const float*)d_in[7];
    const float* a_s_e2o = (const float*)d_in[8];
    const float* a_d_e2o = (const float*)d_in[9];
    const float* a_s_o2o = (const float*)d_in[10];
    const float* a_d_o2o = (const float*)d_in[11];
    const float* klw  = (const float*)d_in[12];
    const float* klb  = (const float*)d_in[13];
    const float* qsem = (const float*)d_in[14];
    const float* linw = (const float*)d_in[15];
    const float* linb = (const float*)d_in[16];
    float* out = (float*)d_out;

    void* p;
    float *h_o, *h_e, *out0, *out1, *asrc, *adst, *amax, *denom, *ebuf, *ksum, *musum;
    cudaGetSymbolAddress(&p, g_h_o);  h_o  = (float*)p;
    cudaGetSymbolAddress(&p, g_h_e);  h_e  = (float*)p;
    cudaGetSymbolAddress(&p, g_out0); out0 = (float*)p;
    cudaGetSymbolAddress(&p, g_out1); out1 = (float*)p;
    cudaGetSymbolAddress(&p, g_asrc); asrc = (float*)p;
    cudaGetSymbolAddress(&p, g_adst); adst = (float*)p;
    cudaGetSymbolAddress(&p, g_amax); amax = (float*)p;
    cudaGetSymbolAddress(&p, g_denom); denom = (float*)p;
    cudaGetSymbolAddress(&p, g_ebuf); ebuf = (float*)p;
    cudaGetSymbolAddress(&p, g_ksum); ksum = (float*)p;
    cudaGetSymbolAddress(&p, g_musum); musum = (float*)p;

    const long ND = (long)NN * DD;
    dim3 ggrid(DD / BN, (NN + BM - 1) / BM);   // (8, 1563)

    // 1. projections
    gemm_kernel<0><<<ggrid, 256>>>(x_o, powm, pob, h_o, NN, nullptr);
    gemm_kernel<0><<<ggrid, 256>>>(x_e, pewm, peb, h_e, NN, nullptr);

    // 2. zero accumulators
    zero_buf<<<4096, 256>>>(out0, ND);
    zero_buf<<<4096, 256>>>(out1, ND);
    zero_buf<<<4, 256>>>(ksum, 2 * DD);
    zero_buf<<<4, 256>>>(musum, 2 * DD);

    int ah_blocks = (NN * 32 + 255) / 256;      // warp per node
    int eh_blocks = (EE * HH + 255) / 256;
    int sc_blocks = (EE * 32 + 255) / 256;      // warp per edge
    int ie_blocks = (NN * HH + 255) / 256;

    // 3. metapath 0: entity -> openie
    compute_ah<<<ah_blocks, 256>>>(h_e, a_s_e2o, asrc, NN);
    compute_ah<<<ah_blocks, 256>>>(h_o, a_d_e2o, adst, NN);
    init_edge_state<<<ie_blocks, 256>>>(amax, denom, NN * HH);
    edge_alpha_max<<<eh_blocks, 256>>>(e2o, e2o + EE, asrc, adst, ebuf, amax, EE);
    edge_exp_sum<<<eh_blocks, 256>>>(e2o + EE, ebuf, amax, denom, EE);
    edge_scatter<<<sc_blocks, 256>>>(e2o, e2o + EE, h_e, ebuf, denom, out0, EE);

    // 4. metapath 1: openie -> openie
    compute_ah<<<ah_blocks, 256>>>(h_o, a_s_o2o, asrc, NN);
    compute_ah<<<ah_blocks, 256>>>(h_o, a_d_o2o, adst, NN);
    init_edge_state<<<ie_blocks, 256>>>(amax, denom, NN * HH);
    edge_alpha_max<<<eh_blocks, 256>>>(o2o, o2o + EE, asrc, adst, ebuf, amax, EE);
    edge_exp_sum<<<eh_blocks, 256>>>(o2o + EE, ebuf, amax, denom, EE);
    edge_scatter<<<sc_blocks, 256>>>(o2o, o2o + EE, h_o, ebuf, denom, out1, EE);

    // 5. column means of relu(out_m)
    mu_kernel<<<128, 512>>>(out0, musum, NN);
    mu_kernel<<<128, 512>>>(out1, musum + DD, NN);

    // 6. semantic-attention k vectors: sum_n tanh(relu(out_m) @ k_lin_w + b)
    gemm_kernel<1><<<ggrid, 256>>>(out0, klw, klb, nullptr, NN, ksum);
    gemm_kernel<1><<<ggrid, 256>>>(out1, klw, klb, nullptr, NN, ksum + DD);

    // 7. softmax over metapaths, pool, final linear
    final_kernel<<<1, 512>>>(qsem, linw, linb, out);
}

// round 2
// speedup vs baseline: 1.0005x; 1.0005x over previous
#include <cuda_runtime.h>
#include <math.h>

#define NN 100000
#define EE 150000
#define DD 512
#define HH 8
#define DHH 64

#define BM 64
#define BN 64
#define BK 16

// ---------------- scratch (static __device__ globals; no allocation) -------
__device__ float g_h_o[(size_t)NN * DD];    // projected openie feats
__device__ float g_h_e[(size_t)NN * DD];    // projected entity feats
__device__ float g_out0[(size_t)NN * DD];   // metapath 0 output (pre-relu sums)
__device__ float g_out1[(size_t)NN * DD];   // metapath 1 output (pre-relu sums)
__device__ float g_asrc[NN * HH];
__device__ float g_adst[NN * HH];
__device__ float g_amax[NN * HH];
__device__ float g_denom[NN * HH];
__device__ float g_ebuf[EE * HH];           // alpha, then exp values
__device__ float g_ksum[2 * DD];            // sum_n tanh(relu(out)@W+b)
__device__ float g_musum[2 * DD];           // sum_n relu(out)

// ---------------- helpers --------------------------------------------------
__device__ __forceinline__ void atomicMaxF(float* addr, float val) {
    int old = __float_as_int(*addr);
    while (__int_as_float(old) < val) {
        int assumed = old;
        old = atomicCAS((int*)addr, assumed, __float_as_int(val));
        if (old == assumed) break;
    }
}

// ---------------- generic zero ---------------------------------------------
__global__ void zero_buf(float* p, long n) {
    long i = (long)blockIdx.x * blockDim.x + threadIdx.x;
    long stride = (long)gridDim.x * blockDim.x;
    for (; i < n; i += stride) p[i] = 0.0f;
}

__global__ void init_edge_state(float* amax, float* denom, int n) {
    int i = blockIdx.x * blockDim.x + threadIdx.x;
    if (i < n) { amax[i] = -INFINITY; denom[i] = 0.0f; }
}

// ---------------- tiled SGEMM: C = A[M,512] @ W[512,512] (+bias) ----------
// MODE 0: store C with bias.
// MODE 1: A is relu'd at load; epilogue accumulates sum_rows tanh(acc+bias)
//         into ksum (C not written).
template <int MODE>
__global__ void gemm_kernel(const float* __restrict__ A,
                            const float* __restrict__ W,
                            const float* __restrict__ bias,
                            float* __restrict__ C, int M,
                            float* __restrict__ ksum_out) {
    __shared__ float As[BK][BM];
    __shared__ float Bs[BK][BN];
    __shared__ float red[16][BN];

    int tid = threadIdx.x;            // 0..255
    int tx = tid & 15, ty = tid >> 4;
    int m0 = blockIdx.y * BM;
    int n0 = blockIdx.x * BN;

    int arow = tid >> 2;              // 0..63
    int acol = (tid & 3) * 4;
    int brow = tid >> 4;              // 0..15
    int bcol = (tid & 15) * 4;

    float acc[4][4];
#pragma unroll
    for (int i = 0; i < 4; i++)
#pragma unroll
        for (int j = 0; j < 4; j++) acc[i][j] = 0.0f;

    for (int k0 = 0; k0 < DD; k0 += BK) {
        int gm = m0 + arow;
        float4 av;
        if (gm < M) {
            av = *(const float4*)(A + (size_t)gm * DD + k0 + acol);
        } else {
            av = make_float4(0.f, 0.f, 0.f, 0.f);
        }
        if (MODE == 1) {
            av.x = fmaxf(av.x, 0.f); av.y = fmaxf(av.y, 0.f);
            av.z = fmaxf(av.z, 0.f); av.w = fmaxf(av.w, 0.f);
        }
        As[acol + 0][arow] = av.x;
        As[acol + 1][arow] = av.y;
        As[acol + 2][arow] = av.z;
        As[acol + 3][arow] = av.w;

        float4 bv = *(const float4*)(W + (size_t)(k0 + brow) * DD + n0 + bcol);
        *(float4*)(&Bs[brow][bcol]) = bv;
        __syncthreads();

#pragma unroll
        for (int k = 0; k < BK; k++) {
            float4 a4 = *(const float4*)(&As[k][ty * 4]);
            float4 b4 = *(const float4*)(&Bs[k][tx * 4]);
            float ar[4] = {a4.x, a4.y, a4.z, a4.w};
            float br[4] = {b4.x, b4.y, b4.z, b4.w};
#pragma unroll
            for (int i = 0; i < 4; i++)
#pragma unroll
                for (int j = 0; j < 4; j++) acc[i][j] += ar[i] * br[j];
        }
        __syncthreads();
    }

    float4 bb = *(const float4*)(bias + n0 + tx * 4);
    float bre[4] = {bb.x, bb.y, bb.z, bb.w};

    if (MODE == 0) {
#pragma unroll
        for (int i = 0; i < 4; i++) {
            int row = m0 + ty * 4 + i;
            if (row < M) {
                float4 v = make_float4(acc[i][0] + bre[0], acc[i][1] + bre[1],
                                       acc[i][2] + bre[2], acc[i][3] + bre[3]);
                *(float4*)(C + (size_t)row * DD + n0 + tx * 4) = v;
            }
        }
    } else {
        float part[4] = {0.f, 0.f, 0.f, 0.f};
#pragma unroll
        for (int i = 0; i < 4; i++) {
            int row = m0 + ty * 4 + i;
            if (row < M) {
#pragma unroll
                for (int j = 0; j < 4; j++)
                    part[j] += tanhf(acc[i][j] + bre[j]);
            }
        }
#pragma unroll
        for (int j = 0; j < 4; j++) red[ty][tx * 4 + j] = part[j];
        __syncthreads();
        if (tid < BN) {
            float s = 0.f;
#pragma unroll
            for (int r = 0; r < 16; r++) s += red[r][tid];
            atomicAdd(&ksum_out[n0 + tid], s);
        }
    }
}

// ---------------- per-node attention dots: a[n,h] = <h[n,h,:], att[h,:]> ----
__global__ void compute_ah(const float* __restrict__ hmat,
                           const float* __restrict__ att,
                           float* __restrict__ a, int n_nodes) {
    int gt = blockIdx.x * blockDim.x + threadIdx.x;
    int warp = gt >> 5;
    int lane = threadIdx.x & 31;
    if (warp >= n_nodes) return;
    int base = lane * 16;                   // h = lane>>2
    const float4* hp = (const float4*)(hmat + (size_t)warp * DD + base);
    const float4* ap = (const float4*)(att + base);
    float s = 0.f;
#pragma unroll
    for (int q = 0; q < 4; q++) {
        float4 hv = hp[q];
        float4 av = ap[q];
        s += hv.x * av.x + hv.y * av.y + hv.z * av.z + hv.w * av.w;
    }
    s += __shfl_xor_sync(0xffffffffu, s, 1);
    s += __shfl_xor_sync(0xffffffffu, s, 2);
    if ((lane & 3) == 0) a[warp * HH + (lane >> 2)] = s;
}

// ---------------- edge pass 1: alpha + segment max --------------------------
__global__ void edge_alpha_max(const int* __restrict__ src,
                               const int* __restrict__ dst,
                               const float* __restrict__ asrc,
                               const float* __restrict__ adst,
                               float* __restrict__ alpha,
                               float* __restrict__ amax, int ne) {
    int i = blockIdx.x * blockDim.x + threadIdx.x;
    if (i >= ne * HH) return;
    int e = i >> 3, h = i & 7;
    float v = asrc[src[e] * HH + h] + adst[dst[e] * HH + h];
    v = (v > 0.f) ? v : 0.2f * v;          // leaky_relu 0.2
    alpha[i] = v;
    atomicMaxF(&amax[dst[e] * HH + h], v);
}

// ---------------- edge pass 2: exp + segment sum -----------------------------
__global__ void edge_exp_sum(const int* __restrict__ dst,
                             float* __restrict__ alpha,
                             const float* __restrict__ amax,
                             float* __restrict__ denom, int ne) {
    int i = blockIdx.x * blockDim.x + threadIdx.x;
    if (i >= ne * HH) return;
    int e = i >> 3, h = i & 7;
    float ex = expf(alpha[i] - amax[dst[e] * HH + h]);
    alpha[i] = ex;
    atomicAdd(&denom[dst[e] * HH + h], ex);
}

// ---------------- edge pass 3: weighted message scatter ----------------------
__global__ void edge_scatter(const int* __restrict__ src,
                             const int* __restrict__ dst,
                             const float* __restrict__ hsrc,
                             const float* __restrict__ exbuf,
                             const float* __restrict__ denom,
                             float* __restrict__ outb, int ne) {
    int gt = blockIdx.x * blockDim.x + threadIdx.x;
    int e = gt >> 5;
    int lane = threadIdx.x & 31;
    if (e >= ne) return;
    int s = src[e], d = dst[e];
    int h = lane >> 2;
    float w = exbuf[e * HH + h] / (denom[d * HH + h] + 1e-16f);
    const float4* hp = (const float4*)(hsrc + (size_t)s * DD + lane * 16);
    float* op = outb + (size_t)d * DD + lane * 16;
#pragma unroll
    for (int q = 0; q < 4; q++) {
        float4 v = hp[q];
        atomicAdd(op + q * 4 + 0, v.x * w);
        atomicAdd(op + q * 4 + 1, v.y * w);
        atomicAdd(op + q * 4 + 2, v.z * w);
        atomicAdd(op + q * 4 + 3, v.w * w);
    }
}

// ---------------- column means of relu(out) ----------------------------------
__global__ void mu_kernel(const float* __restrict__ outb,
                          float* __restrict__ musum, int M) {
    int f = threadIdx.x;                   // 512 threads
    int chunk = (M + gridDim.x - 1) / gridDim.x;
    int r0 = blockIdx.x * chunk;
    int r1 = min(M, r0 + chunk);
    float acc = 0.f;
    for (int r = r0; r < r1; r++)
        acc += fmaxf(outb[(size_t)r * DD + f], 0.f);
    atomicAdd(&musum[f], acc);
}

// ---------------- final semantic attention + pool + linear -------------------
__global__ void final_kernel(const float* __restrict__ qsem,
                             const float* __restrict__ linw,
                             const float* __restrict__ linb,
                             float* __restrict__ out) {
    __shared__ float sh[DD];
    __shared__ float sv[2];
    int f = threadIdx.x;                   // 512 threads
    const float invN = 1.0f / (float)NN;
    float q = qsem[f];
    float v0 = g_ksum[f] * invN * q;
    float v1 = g_ksum[DD + f] * invN * q;

    sh[f] = v0; __syncthreads();
    for (int s = 256; s > 0; s >>= 1) { if (f < s) sh[f] += sh[f + s]; __syncthreads(); }
    if (f == 0) sv[0] = sh[0];
    __syncthreads();
    sh[f] = v1; __syncthreads();
    for (int s = 256; s > 0; s >>= 1) { if (f < s) sh[f] += sh[f + s]; __syncthreads(); }
    if (f == 0) sv[1] = sh[0];
    __syncthreads();

    float s0 = sv[0], s1 = sv[1];
    float mx = fmaxf(s0, s1);
    float e0 = expf(s0 - mx), e1 = expf(s1 - mx);
    float sem0 = e0 / (e0 + e1), sem1 = e1 / (e0 + e1);

    float pooled = (sem0 * g_musum[f] + sem1 * g_musum[DD + f]) * invN;
    float w0 = pooled * linw[f * 2 + 0];
    float w1 = pooled * linw[f * 2 + 1];

    sh[f] = w0; __syncthreads();
    for (int s = 256; s > 0; s >>= 1) { if (f < s) sh[f] += sh[f + s]; __syncthreads(); }
    if (f == 0) out[0] = sh[0] + linb[0];
    __syncthreads();
    sh[f] = w1; __syncthreads();
    for (int s = 256; s > 0; s >>= 1) { if (f < s) sh[f] += sh[f + s]; __syncthreads(); }
    if (f == 0) out[1] = sh[0] + linb[1];
}

// ---------------- host launcher ---------------------------------------------
extern "C" void kernel_launch(void* const* d_in, const int* in_sizes, int n_in,
                              void* d_out, int out_size) {
    const float* x_o  = (const float*)d_in[0];
    const float* x_e  = (const float*)d_in[1];
    const int*   e2o  = (const int*)d_in[2];   // [2,E]
    const int*   o2o  = (const int*)d_in[3];
    const float* powm = (const float*)d_in[4];
    const float* pob  = (const float*)d_in[5];
    const float* pewm = (const float*)d_in[6];
    const float* peb  = (const float*)d_in[7];
    const float* a_s_e2o = (const float*)d_in[8];
    const float* a_d_e2o = (const float*)d_in[9];
    const float* a_s_o2o = (const float*)d_in[10];
    const float* a_d_o2o = (const float*)d_in[11];
    const float* klw  = (const float*)d_in[12];
    const float* klb  = (const float*)d_in[13];
    const float* qsem = (const float*)d_in[14];
    const float* linw = (const float*)d_in[15];
    const float* linb = (const float*)d_in[16];
    float* out = (float*)d_out;

    void* p;
    float *h_o, *h_e, *out0, *out1, *asrc, *adst, *amax, *denom, *ebuf, *ksum, *musum;
    cudaGetSymbolAddress(&p, g_h_o);  h_o  = (float*)p;
    cudaGetSymbolAddress(&p, g_h_e);  h_e  = (float*)p;
    cudaGetSymbolAddress(&p, g_out0); out0 = (float*)p;
    cudaGetSymbolAddress(&p, g_out1); out1 = (float*)p;
    cudaGetSymbolAddress(&p, g_asrc); asrc = (float*)p;
    cudaGetSymbolAddress(&p, g_adst); adst = (float*)p;
    cudaGetSymbolAddress(&p, g_amax); amax = (float*)p;
    cudaGetSymbolAddress(&p, g_denom); denom = (float*)p;
    cudaGetSymbolAddress(&p, g_ebuf); ebuf = (float*)p;
    cudaGetSymbolAddress(&p, g_ksum); ksum = (float*)p;
    cudaGetSymbolAddress(&p, g_musum); musum = (float*)p;

    const long ND = (long)NN * DD;
    dim3 ggrid(DD / BN, (NN + BM - 1) / BM);   // (8, 1563)

    // 1. projections
    gemm_kernel<0><<<ggrid, 256>>>(x_o, powm, pob, h_o, NN, nullptr);
    gemm_kernel<0><<<ggrid, 256>>>(x_e, pewm, peb, h_e, NN, nullptr);

    // 2. zero accumulators
    zero_buf<<<4096, 256>>>(out0, ND);
    zero_buf<<<4096, 256>>>(out1, ND);
    zero_buf<<<4, 256>>>(ksum, 2 * DD);
    zero_buf<<<4, 256>>>(musum, 2 * DD);

    int ah_blocks = (NN * 32 + 255) / 256;      // warp per node
    int eh_blocks = (EE * HH + 255) / 256;
    int sc_blocks = (EE * 32 + 255) / 256;      // warp per edge
    int ie_blocks = (NN * HH + 255) / 256;

    // 3. metapath 0: entity -> openie
    compute_ah<<<ah_blocks, 256>>>(h_e, a_s_e2o, asrc, NN);
    compute_ah<<<ah_blocks, 256>>>(h_o, a_d_e2o, adst, NN);
    init_edge_state<<<ie_blocks, 256>>>(amax, denom, NN * HH);
    edge_alpha_max<<<eh_blocks, 256>>>(e2o, e2o + EE, asrc, adst, ebuf, amax, EE);
    edge_exp_sum<<<eh_blocks, 256>>>(e2o + EE, ebuf, amax, denom, EE);
    edge_scatter<<<sc_blocks, 256>>>(e2o, e2o + EE, h_e, ebuf, denom, out0, EE);

    // 4. metapath 1: openie -> openie
    compute_ah<<<ah_blocks, 256>>>(h_o, a_s_o2o, asrc, NN);
    compute_ah<<<ah_blocks, 256>>>(h_o, a_d_o2o, adst, NN);
    init_edge_state<<<ie_blocks, 256>>>(amax, denom, NN * HH);
    edge_alpha_max<<<eh_blocks, 256>>>(o2o, o2o + EE, asrc, adst, ebuf, amax, EE);
    edge_exp_sum<<<eh_blocks, 256>>>(o2o + EE, ebuf, amax, denom, EE);
    edge_scatter<<<sc_blocks, 256>>>(o2o, o2o + EE, h_o, ebuf, denom, out1, EE);

    // 5. column means of relu(out_m)
    mu_kernel<<<128, 512>>>(out0, musum, NN);
    mu_kernel<<<128, 512>>>(out1, musum + DD, NN);

    // 6. semantic-attention k vectors: sum_n tanh(relu(out_m) @ k_lin_w + b)
    gemm_kernel<1><<<ggrid, 256>>>(out0, klw, klb, nullptr, NN, ksum);
    gemm_kernel<1><<<ggrid, 256>>>(out1, klw, klb, nullptr, NN, ksum + DD);

    // 7. softmax over metapaths, pool, final linear
    final_kernel<<<1, 512>>>(qsem, linw, linb, out);
}

// round 3
// speedup vs baseline: 1.4281x; 1.4274x over previous
#include <cuda_runtime.h>
#include <math.h>
#include <mma.h>

using namespace nvcuda;

#define NN 100000
#define EE 150000
#define DD 512
#define HH 8

// GEMM tile config (tensor-core path)
#define GBM 128
#define GBN 128
#define GBK 32
#define APAD 8   // As row stride 40 floats = 160B (32B-aligned rows)
#define BPAD 8   // Bs row stride 136 floats = 544B (32B-aligned rows)

// ---------------- scratch (static __device__ globals; no allocation) -------
__device__ float g_h_o[(size_t)NN * DD];
__device__ float g_h_e[(size_t)NN * DD];
__device__ float g_out0[(size_t)NN * DD];
__device__ float g_out1[(size_t)NN * DD];
__device__ float g_asrc[NN * HH];
__device__ float g_adst[NN * HH];
__device__ float g_amax[NN * HH];
__device__ float g_denom[NN * HH];
__device__ float g_ebuf[EE * HH];
__device__ float g_ksum[2 * DD];
__device__ float g_musum[2 * DD];

// ---------------- helpers --------------------------------------------------
__device__ __forceinline__ void atomicMaxF(float* addr, float val) {
    int old = __float_as_int(*addr);
    while (__int_as_float(old) < val) {
        int assumed = old;
        old = atomicCAS((int*)addr, assumed, __float_as_int(val));
        if (old == assumed) break;
    }
}

__global__ void zero_buf(float* p, long n) {
    long i = (long)blockIdx.x * blockDim.x + threadIdx.x;
    long stride = (long)gridDim.x * blockDim.x;
    for (; i < n; i += stride) p[i] = 0.0f;
}

__global__ void init_edge_state(float* amax, float* denom, int n) {
    int i = blockIdx.x * blockDim.x + threadIdx.x;
    if (i < n) { amax[i] = -INFINITY; denom[i] = 0.0f; }
}

// ---------------- TF32 tensor-core GEMM: C = A[M,512] @ W[512,512] (+bias) --
// MODE 0: C = A@W + bias (stored).
// MODE 1: A relu'd at load; epilogue accumulates sum_rows tanh(acc+bias) into
//         ksum_out (C not written).
template <int MODE>
__global__ void __launch_bounds__(256) gemm_tc(
        const float* __restrict__ A, const float* __restrict__ W,
        const float* __restrict__ bias, float* __restrict__ C, int M,
        float* __restrict__ ksum_out) {
    __shared__ float As[GBM][GBK + APAD];      // 128 x 40
    __shared__ float Bs[GBK][GBN + BPAD];      // 32 x 136
    __shared__ float stage[8][16][20];         // per-warp 16x16 epilogue staging
    __shared__ float ksred[GBN];

    int tid = threadIdx.x;
    int wid = tid >> 5;
    int lane = tid & 31;
    int warp_m = wid & 3;        // 0..3 -> 32-row slab
    int warp_n = wid >> 2;       // 0..1 -> 64-col slab
    int m0 = blockIdx.y * GBM;
    int n0 = blockIdx.x * GBN;
    int wm0 = warp_m * 32;
    int wn0 = warp_n * 64;

    if (MODE == 1 && tid < GBN) ksred[tid] = 0.0f;

    wmma::fragment<wmma::accumulator, 16, 16, 8, float> acc[2][4];
#pragma unroll
    for (int i = 0; i < 2; i++)
#pragma unroll
        for (int j = 0; j < 4; j++) wmma::fill_fragment(acc[i][j], 0.0f);

    for (int k0 = 0; k0 < DD; k0 += GBK) {
        // Load A tile: 128x32 floats = 1024 float4
#pragma unroll
        for (int it = 0; it < 4; it++) {
            int idx = tid + it * 256;
            int row = idx >> 3;
            int c4 = (idx & 7) << 2;
            int gm = m0 + row;
            float4 v = make_float4(0.f, 0.f, 0.f, 0.f);
            if (gm < M) v = *(const float4*)(A + (size_t)gm * DD + k0 + c4);
            if (MODE == 1) {
                v.x = fmaxf(v.x, 0.f); v.y = fmaxf(v.y, 0.f);
                v.z = fmaxf(v.z, 0.f); v.w = fmaxf(v.w, 0.f);
            }
            *(float4*)(&As[row][c4]) = v;
        }
        // Load B tile: 32x128 floats = 1024 float4
#pragma unroll
        for (int it = 0; it < 4; it++) {
            int idx = tid + it * 256;
            int row = idx >> 5;
            int c4 = (idx & 31) << 2;
            float4 v = *(const float4*)(W + (size_t)(k0 + row) * DD + n0 + c4);
            *(float4*)(&Bs[row][c4]) = v;
        }
        __syncthreads();

#pragma unroll
        for (int kk = 0; kk < GBK; kk += 8) {
            wmma::fragment<wmma::matrix_a, 16, 16, 8, wmma::precision::tf32,
                           wmma::row_major> af[2];
            wmma::fragment<wmma::matrix_b, 16, 16, 8, wmma::precision::tf32,
                           wmma::row_major> bf[4];
#pragma unroll
            for (int i = 0; i < 2; i++) {
                wmma::load_matrix_sync(af[i], &As[wm0 + i * 16][kk], GBK + APAD);
#pragma unroll
                for (int t = 0; t < af[i].num_elements; t++)
                    af[i].x[t] = wmma::__float_to_tf32(af[i].x[t]);
            }
#pragma unroll
            for (int j = 0; j < 4; j++) {
                wmma::load_matrix_sync(bf[j], &Bs[kk][wn0 + j * 16], GBN + BPAD);
#pragma unroll
                for (int t = 0; t < bf[j].num_elements; t++)
                    bf[j].x[t] = wmma::__float_to_tf32(bf[j].x[t]);
            }
#pragma unroll
            for (int i = 0; i < 2; i++)
#pragma unroll
                for (int j = 0; j < 4; j++)
                    wmma::mma_sync(acc[i][j], af[i], bf[j], acc[i][j]);
        }
        __syncthreads();
    }

    // ---------------- epilogue ----------------
    int r = lane >> 1;
    int cbase = (lane & 1) * 8;
#pragma unroll
    for (int i = 0; i < 2; i++) {
#pragma unroll
        for (int j = 0; j < 4; j++) {
            wmma::store_matrix_sync(&stage[wid][0][0], acc[i][j], 20,
                                    wmma::mem_row_major);
            __syncwarp();
            int grow = m0 + wm0 + i * 16 + r;
            int gcol = n0 + wn0 + j * 16 + cbase;
            if (grow < M) {
                float4 v1 = *(const float4*)(&stage[wid][r][cbase]);
                float4 v2 = *(const float4*)(&stage[wid][r][cbase + 4]);
                float4 b1 = *(const float4*)(bias + gcol);
                float4 b2 = *(const float4*)(bias + gcol + 4);
                v1.x += b1.x; v1.y += b1.y; v1.z += b1.z; v1.w += b1.w;
                v2.x += b2.x; v2.y += b2.y; v2.z += b2.z; v2.w += b2.w;
                if (MODE == 0) {
                    *(float4*)(C + (size_t)grow * DD + gcol) = v1;
                    *(float4*)(C + (size_t)grow * DD + gcol + 4) = v2;
                } else {
                    float s = tanhf(v1.x) + tanhf(v1.y) + tanhf(v1.z) + tanhf(v1.w);
                    float s2 = tanhf(v2.x) + tanhf(v2.y) + tanhf(v2.z) + tanhf(v2.w);
                    int lc = wn0 + j * 16 + cbase;
                    atomicAdd(&ksred[lc + 0], tanhf(v1.x));
                    atomicAdd(&ksred[lc + 1], tanhf(v1.y));
                    atomicAdd(&ksred[lc + 2], tanhf(v1.z));
                    atomicAdd(&ksred[lc + 3], tanhf(v1.w));
                    atomicAdd(&ksred[lc + 4], tanhf(v2.x));
                    atomicAdd(&ksred[lc + 5], tanhf(v2.y));
                    atomicAdd(&ksred[lc + 6], tanhf(v2.z));
                    atomicAdd(&ksred[lc + 7], tanhf(v2.w));
                    (void)s; (void)s2;
                }
            }
            __syncwarp();
        }
    }
    if (MODE == 1) {
        __syncthreads();
        if (tid < GBN) atomicAdd(&ksum_out[n0 + tid], ksred[tid]);
    }
}

// ---------------- per-node attention dots -----------------------------------
__global__ void compute_ah(const float* __restrict__ hmat,
                           const float* __restrict__ att,
                           float* __restrict__ a, int n_nodes) {
    int gt = blockIdx.x * blockDim.x + threadIdx.x;
    int warp = gt >> 5;
    int lane = threadIdx.x & 31;
    if (warp >= n_nodes) return;
    int base = lane * 16;
    const float4* hp = (const float4*)(hmat + (size_t)warp * DD + base);
    const float4* ap = (const float4*)(att + base);
    float s = 0.f;
#pragma unroll
    for (int q = 0; q < 4; q++) {
        float4 hv = hp[q];
        float4 av = ap[q];
        s += hv.x * av.x + hv.y * av.y + hv.z * av.z + hv.w * av.w;
    }
    s += __shfl_xor_sync(0xffffffffu, s, 1);
    s += __shfl_xor_sync(0xffffffffu, s, 2);
    if ((lane & 3) == 0) a[warp * HH + (lane >> 2)] = s;
}

// ---------------- edge pass 1: alpha + segment max --------------------------
__global__ void edge_alpha_max(const int* __restrict__ src,
                               const int* __restrict__ dst,
                               const float* __restrict__ asrc,
                               const float* __restrict__ adst,
                               float* __restrict__ alpha,
                               float* __restrict__ amax, int ne) {
    int i = blockIdx.x * blockDim.x + threadIdx.x;
    if (i >= ne * HH) return;
    int e = i >> 3, h = i & 7;
    float v = asrc[src[e] * HH + h] + adst[dst[e] * HH + h];
    v = (v > 0.f) ? v : 0.2f * v;
    alpha[i] = v;
    atomicMaxF(&amax[dst[e] * HH + h], v);
}

// ---------------- edge pass 2: exp + segment sum -----------------------------
__global__ void edge_exp_sum(const int* __restrict__ dst,
                             float* __restrict__ alpha,
                             const float* __restrict__ amax,
                             float* __restrict__ denom, int ne) {
    int i = blockIdx.x * blockDim.x + threadIdx.x;
    if (i >= ne * HH) return;
    int e = i >> 3, h = i & 7;
    float ex = expf(alpha[i] - amax[dst[e] * HH + h]);
    alpha[i] = ex;
    atomicAdd(&denom[dst[e] * HH + h], ex);
}

// ---------------- edge pass 3: weighted scatter (vector red) -----------------
__global__ void edge_scatter(const int* __restrict__ src,
                             const int* __restrict__ dst,
                             const float* __restrict__ hsrc,
                             const float* __restrict__ exbuf,
                             const float* __restrict__ denom,
                             float* __restrict__ outb, int ne) {
    int gt = blockIdx.x * blockDim.x + threadIdx.x;
    int e = gt >> 5;
    int lane = threadIdx.x & 31;
    if (e >= ne) return;
    int s = src[e], d = dst[e];
    int h = lane >> 2;
    float w = exbuf[e * HH + h] / (denom[d * HH + h] + 1e-16f);
    const float4* hp = (const float4*)(hsrc + (size_t)s * DD + lane * 16);
    float* op = outb + (size_t)d * DD + lane * 16;
#pragma unroll
    for (int q = 0; q < 4; q++) {
        float4 v = hp[q];
        asm volatile("red.global.add.v4.f32 [%0], {%1, %2, %3, %4};"
                     :: "l"(op + q * 4), "f"(v.x * w), "f"(v.y * w),
                        "f"(v.z * w), "f"(v.w * w)
                     : "memory");
    }
}

// ---------------- column means of relu(out) ----------------------------------
__global__ void mu_kernel(const float* __restrict__ outb,
                          float* __restrict__ musum, int M) {
    int f = threadIdx.x;
    int chunk = (M + gridDim.x - 1) / gridDim.x;
    int r0 = blockIdx.x * chunk;
    int r1 = min(M, r0 + chunk);
    float acc = 0.f;
    for (int r = r0; r < r1; r++)
        acc += fmaxf(outb[(size_t)r * DD + f], 0.f);
    atomicAdd(&musum[f], acc);
}

// ---------------- final semantic attention + pool + linear -------------------
__global__ void final_kernel(const float* __restrict__ qsem,
                             const float* __restrict__ linw,
                             const float* __restrict__ linb,
                             float* __restrict__ out) {
    __shared__ float sh[DD];
    __shared__ float sv[2];
    int f = threadIdx.x;
    const float invN = 1.0f / (float)NN;
    float q = qsem[f];
    float v0 = g_ksum[f] * invN * q;
    float v1 = g_ksum[DD + f] * invN * q;

    sh[f] = v0; __syncthreads();
    for (int s = 256; s > 0; s >>= 1) { if (f < s) sh[f] += sh[f + s]; __syncthreads(); }
    if (f == 0) sv[0] = sh[0];
    __syncthreads();
    sh[f] = v1; __syncthreads();
    for (int s = 256; s > 0; s >>= 1) { if (f < s) sh[f] += sh[f + s]; __syncthreads(); }
    if (f == 0) sv[1] = sh[0];
    __syncthreads();

    float s0 = sv[0], s1 = sv[1];
    float mx = fmaxf(s0, s1);
    float e0 = expf(s0 - mx), e1 = expf(s1 - mx);
    float sem0 = e0 / (e0 + e1), sem1 = e1 / (e0 + e1);

    float pooled = (sem0 * g_musum[f] + sem1 * g_musum[DD + f]) * invN;
    float w0 = pooled * linw[f * 2 + 0];
    float w1 = pooled * linw[f * 2 + 1];

    sh[f] = w0; __syncthreads();
    for (int s = 256; s > 0; s >>= 1) { if (f < s) sh[f] += sh[f + s]; __syncthreads(); }
    if (f == 0) out[0] = sh[0] + linb[0];
    __syncthreads();
    sh[f] = w1; __syncthreads();
    for (int s = 256; s > 0; s >>= 1) { if (f < s) sh[f] += sh[f + s]; __syncthreads(); }
    if (f == 0) out[1] = sh[0] + linb[1];
}

// ---------------- host launcher ---------------------------------------------
extern "C" void kernel_launch(void* const* d_in, const int* in_sizes, int n_in,
                              void* d_out, int out_size) {
    const float* x_o  = (const float*)d_in[0];
    const float* x_e  = (const float*)d_in[1];
    const int*   e2o  = (const int*)d_in[2];
    const int*   o2o  = (const int*)d_in[3];
    const float* powm = (const float*)d_in[4];
    const float* pob  = (const float*)d_in[5];
    const float* pewm = (const float*)d_in[6];
    const float* peb  = (const float*)d_in[7];
    const float* a_s_e2o = (const float*)d_in[8];
    const float* a_d_e2o = (const float*)d_in[9];
    const float* a_s_o2o = (const float*)d_in[10];
    const float* a_d_o2o = (const float*)d_in[11];
    const float* klw  = (const float*)d_in[12];
    const float* klb  = (const float*)d_in[13];
    const float* qsem = (const float*)d_in[14];
    const float* linw = (const float*)d_in[15];
    const float* linb = (const float*)d_in[16];
    float* out = (float*)d_out;

    void* p;
    float *h_o, *h_e, *out0, *out1, *asrc, *adst, *amax, *denom, *ebuf, *ksum, *musum;
    cudaGetSymbolAddress(&p, g_h_o);  h_o  = (float*)p;
    cudaGetSymbolAddress(&p, g_h_e);  h_e  = (float*)p;
    cudaGetSymbolAddress(&p, g_out0); out0 = (float*)p;
    cudaGetSymbolAddress(&p, g_out1); out1 = (float*)p;
    cudaGetSymbolAddress(&p, g_asrc); asrc = (float*)p;
    cudaGetSymbolAddress(&p, g_adst); adst = (float*)p;
    cudaGetSymbolAddress(&p, g_amax); amax = (float*)p;
    cudaGetSymbolAddress(&p, g_denom); denom = (float*)p;
    cudaGetSymbolAddress(&p, g_ebuf); ebuf = (float*)p;
    cudaGetSymbolAddress(&p, g_ksum); ksum = (float*)p;
    cudaGetSymbolAddress(&p, g_musum); musum = (float*)p;

    const long ND = (long)NN * DD;
    dim3 tcgrid(DD / GBN, (NN + GBM - 1) / GBM);   // (4, 782)

    // 1. projections (tensor cores, tf32)
    gemm_tc<0><<<tcgrid, 256>>>(x_o, powm, pob, h_o, NN, nullptr);
    gemm_tc<0><<<tcgrid, 256>>>(x_e, pewm, peb, h_e, NN, nullptr);

    // 2. zero accumulators
    zero_buf<<<4096, 256>>>(out0, ND);
    zero_buf<<<4096, 256>>>(out1, ND);
    zero_buf<<<4, 256>>>(ksum, 2 * DD);
    zero_buf<<<4, 256>>>(musum, 2 * DD);

    int ah_blocks = (NN * 32 + 255) / 256;
    int eh_blocks = (EE * HH + 255) / 256;
    int sc_blocks = (EE * 32 + 255) / 256;
    int ie_blocks = (NN * HH + 255) / 256;

    // 3. metapath 0: entity -> openie
    compute_ah<<<ah_blocks, 256>>>(h_e, a_s_e2o, asrc, NN);
    compute_ah<<<ah_blocks, 256>>>(h_o, a_d_e2o, adst, NN);
    init_edge_state<<<ie_blocks, 256>>>(amax, denom, NN * HH);
    edge_alpha_max<<<eh_blocks, 256>>>(e2o, e2o + EE, asrc, adst, ebuf, amax, EE);
    edge_exp_sum<<<eh_blocks, 256>>>(e2o + EE, ebuf, amax, denom, EE);
    edge_scatter<<<sc_blocks, 256>>>(e2o, e2o + EE, h_e, ebuf, denom, out0, EE);

    // 4. metapath 1: openie -> openie
    compute_ah<<<ah_blocks, 256>>>(h_o, a_s_o2o, asrc, NN);
    compute_ah<<<ah_blocks, 256>>>(h_o, a_d_o2o, adst, NN);
    init_edge_state<<<ie_blocks, 256>>>(amax, denom, NN * HH);
    edge_alpha_max<<<eh_blocks, 256>>>(o2o, o2o + EE, asrc, adst, ebuf, amax, EE);
    edge_exp_sum<<<eh_blocks, 256>>>(o2o + EE, ebuf, amax, denom, EE);
    edge_scatter<<<sc_blocks, 256>>>(o2o, o2o + EE, h_o, ebuf, denom, out1, EE);

    // 5. column means of relu(out_m)
    mu_kernel<<<128, 512>>>(out0, musum, NN);
    mu_kernel<<<128, 512>>>(out1, musum + DD, NN);

    // 6. semantic-attention k vectors: sum_n tanh(relu(out_m) @ k_lin_w + b)
    gemm_tc<1><<<tcgrid, 256>>>(out0, klw, klb, nullptr, NN, ksum);
    gemm_tc<1><<<tcgrid, 256>>>(out1, klw, klb, nullptr, NN, ksum + DD);

    // 7. softmax over metapaths, pool, final linear
    final_kernel<<<1, 512>>>(qsem, linw, linb, out);
}